// round 1
// baseline (speedup 1.0000x reference)
#include <cuda_runtime.h>
#include <math.h>

#define LEN 13294
#define TOK (2 * LEN)
#define D 256
#define NH 8
#define DH 32
#define DFF 1024
#define EPS 1e-5f

// ---------------- scratch (device globals; no allocation allowed) ----------------
__device__ float g_Q[TOK * D];      // src + pos
__device__ float g_V[TOK * D];      // value projection
__device__ float g_OFF[TOK * D];    // sampling offsets (NH*NL*NP*2 = 256)
__device__ float g_LOG[TOK * 128];  // attention logits (NH*NL*NP = 128)
__device__ float g_AOUT[TOK * D];   // deform-attn per-head output
__device__ float g_X1[TOK * D];     // after first residual+LN
__device__ float g_H[TOK * DFF];    // FFN hidden
__device__ float g_Y[TOK * D];      // generic 256-wide scratch

__constant__ int c_HW[4] = {100, 50, 25, 13};        // H==W per level
__constant__ int c_S[4]  = {0, 10000, 12500, 13125}; // level starts

// ---------------- elementwise add (float4) ----------------
__global__ __launch_bounds__(256) void add_kernel(const float* __restrict__ a,
                                                  const float* __restrict__ b,
                                                  float* __restrict__ o, int n4) {
    int i = blockIdx.x * blockDim.x + threadIdx.x;
    if (i >= n4) return;
    float4 va = ((const float4*)a)[i];
    float4 vb = ((const float4*)b)[i];
    va.x += vb.x; va.y += vb.y; va.z += vb.z; va.w += vb.w;
    ((float4*)o)[i] = va;
}

// ---------------- tiled SGEMM: C[M,N] = A[M,K] @ B[K,N] + bias, optional relu ----
// 64x64 block tile, K-tile 16, 256 threads, 4x4 microtile.
__global__ __launch_bounds__(256) void sgemm_bias(const float* __restrict__ A,
                                                  const float* __restrict__ Bw,
                                                  const float* __restrict__ bias,
                                                  float* __restrict__ C,
                                                  int M, int N, int K, int relu) {
    __shared__ float As[64][17];   // [row][k] padded
    __shared__ float Bs[16][64];   // [k][col]
    int tid = threadIdx.x;
    int tx = tid & 15;             // 0..15 -> col group
    int ty = tid >> 4;             // 0..15 -> row group
    int row0 = blockIdx.y * 64;
    int col0 = blockIdx.x * 64;

    float acc[4][4];
#pragma unroll
    for (int i = 0; i < 4; i++)
#pragma unroll
        for (int j = 0; j < 4; j++) acc[i][j] = 0.f;

    for (int k0 = 0; k0 < K; k0 += 16) {
        // load A tile: 64 rows x 16 k  (coalesced global, conflict-free smem store)
#pragma unroll
        for (int i = 0; i < 4; i++) {
            int e = tid + i * 256;        // 0..1023
            int r = e >> 4, c = e & 15;
            int gr = row0 + r;
            As[r][c] = (gr < M) ? A[(size_t)gr * K + k0 + c] : 0.f;
        }
        // load B tile: 16 k x 64 cols
#pragma unroll
        for (int i = 0; i < 4; i++) {
            int e = tid + i * 256;
            int r = e >> 6, c = e & 63;
            Bs[r][c] = Bw[(size_t)(k0 + r) * N + col0 + c];
        }
        __syncthreads();
#pragma unroll
        for (int kk = 0; kk < 16; kk++) {
            float a[4], b[4];
#pragma unroll
            for (int i = 0; i < 4; i++) a[i] = As[ty * 4 + i][kk];
#pragma unroll
            for (int j = 0; j < 4; j++) b[j] = Bs[kk][tx * 4 + j];
#pragma unroll
            for (int i = 0; i < 4; i++)
#pragma unroll
                for (int j = 0; j < 4; j++) acc[i][j] += a[i] * b[j];
        }
        __syncthreads();
    }

#pragma unroll
    for (int i = 0; i < 4; i++) {
        int gr = row0 + ty * 4 + i;
        if (gr >= M) continue;
#pragma unroll
        for (int j = 0; j < 4; j++) {
            int gc = col0 + tx * 4 + j;
            float v = acc[i][j] + bias[gc];
            if (relu) v = fmaxf(v, 0.f);
            C[(size_t)gr * N + gc] = v;
        }
    }
}

// ---------------- deformable sampling: one warp per (token, head) ----------------
__global__ __launch_bounds__(256) void sample_kernel(const float* __restrict__ refpts) {
    int g = blockIdx.x * 8 + (threadIdx.x >> 5);
    int lane = threadIdx.x & 31;
    if (g >= TOK * NH) return;
    int t = g >> 3;       // token (b*LEN + q)
    int h = g & 7;
    int b = t / LEN;

    // softmax over 16 logits (redundant per lane; trivially cheap)
    const float* lg = g_LOG + (size_t)t * 128 + h * 16;
    float m = -1e30f;
    float e[16];
#pragma unroll
    for (int i = 0; i < 16; i++) m = fmaxf(m, lg[i]);
    float s = 0.f;
#pragma unroll
    for (int i = 0; i < 16; i++) { e[i] = __expf(lg[i] - m); s += e[i]; }
    float inv = 1.f / s;

    const float* offp = g_OFF + (size_t)t * 256 + h * 32;
    float acc = 0.f;

#pragma unroll
    for (int l = 0; l < 4; l++) {
        int Wi = c_HW[l];
        int Hi = Wi;
        float Wf = (float)Wi, Hf = (float)Hi;
        float rx = refpts[(size_t)t * 8 + l * 2 + 0];
        float ry = refpts[(size_t)t * 8 + l * 2 + 1];
        const float* vbase = g_V + ((size_t)(b * LEN + c_S[l])) * 256 + h * 32;
#pragma unroll
        for (int p = 0; p < 4; p++) {
            float aw = e[l * 4 + p] * inv;
            float x = rx * Wf + offp[l * 8 + p * 2 + 0] - 0.5f;
            float y = ry * Hf + offp[l * 8 + p * 2 + 1] - 0.5f;
            float x0f = floorf(x), y0f = floorf(y);
            float dx = x - x0f, dy = y - y0f;
            int x0 = (int)x0f, y0 = (int)y0f;
            float w00 = (1.f - dx) * (1.f - dy) * aw;
            float w10 = dx * (1.f - dy) * aw;
            float w01 = (1.f - dx) * dy * aw;
            float w11 = dx * dy * aw;
            // corner (x0, y0)
            if (x0 >= 0 && x0 < Wi && y0 >= 0 && y0 < Hi)
                acc += w00 * vbase[(size_t)(y0 * Wi + x0) * 256 + lane];
            // corner (x0+1, y0)
            if (x0 + 1 >= 0 && x0 + 1 < Wi && y0 >= 0 && y0 < Hi)
                acc += w10 * vbase[(size_t)(y0 * Wi + x0 + 1) * 256 + lane];
            // corner (x0, y0+1)
            if (x0 >= 0 && x0 < Wi && y0 + 1 >= 0 && y0 + 1 < Hi)
                acc += w01 * vbase[(size_t)((y0 + 1) * Wi + x0) * 256 + lane];
            // corner (x0+1, y0+1)
            if (x0 + 1 >= 0 && x0 + 1 < Wi && y0 + 1 >= 0 && y0 + 1 < Hi)
                acc += w11 * vbase[(size_t)((y0 + 1) * Wi + x0 + 1) * 256 + lane];
        }
    }
    g_AOUT[(size_t)t * 256 + h * 32 + lane] = acc;
}

// ---------------- residual + layernorm: one warp per token, D=256 -----------------
__global__ __launch_bounds__(256) void resid_ln(const float* __restrict__ a,
                                                const float* __restrict__ r,
                                                const float* __restrict__ gam,
                                                const float* __restrict__ bet,
                                                float* __restrict__ out) {
    int t = blockIdx.x * 8 + (threadIdx.x >> 5);
    int lane = threadIdx.x & 31;
    if (t >= TOK) return;
    size_t base = (size_t)t * 256 + lane * 8;
    float v[8];
    float s = 0.f;
#pragma unroll
    for (int i = 0; i < 8; i++) {
        v[i] = a[base + i] + r[base + i];
        s += v[i];
    }
#pragma unroll
    for (int o = 16; o > 0; o >>= 1) s += __shfl_xor_sync(0xffffffffu, s, o);
    float mean = s * (1.f / 256.f);
    float s2 = 0.f;
#pragma unroll
    for (int i = 0; i < 8; i++) {
        float d = v[i] - mean;
        s2 += d * d;
    }
#pragma unroll
    for (int o = 16; o > 0; o >>= 1) s2 += __shfl_xor_sync(0xffffffffu, s2, o);
    float rstd = rsqrtf(s2 * (1.f / 256.f) + EPS);
#pragma unroll
    for (int i = 0; i < 8; i++) {
        int c = lane * 8 + i;
        out[base + i] = (v[i] - mean) * rstd * gam[c] + bet[c];
    }
}

// ---------------- launch ----------------
extern "C" void kernel_launch(void* const* d_in, const int* in_sizes, int n_in,
                              void* d_out, int out_size) {
    const float* src   = (const float*)d_in[0];
    const float* pos   = (const float*)d_in[1];
    const float* refp  = (const float*)d_in[2];
    const float* Wv    = (const float*)d_in[3];
    const float* bv    = (const float*)d_in[4];
    const float* Woff  = (const float*)d_in[5];
    const float* boff  = (const float*)d_in[6];
    const float* Wattn = (const float*)d_in[7];
    const float* battn = (const float*)d_in[8];
    const float* Wout  = (const float*)d_in[9];
    const float* bout  = (const float*)d_in[10];
    const float* W1    = (const float*)d_in[11];
    const float* b1    = (const float*)d_in[12];
    const float* W2    = (const float*)d_in[13];
    const float* b2    = (const float*)d_in[14];
    const float* g1    = (const float*)d_in[15];
    const float* be1   = (const float*)d_in[16];
    const float* g2    = (const float*)d_in[17];
    const float* be2   = (const float*)d_in[18];
    float* out = (float*)d_out;

    float *Q, *V, *OFF, *LOG, *AOUT, *X1, *H, *Y;
    cudaGetSymbolAddress((void**)&Q, g_Q);
    cudaGetSymbolAddress((void**)&V, g_V);
    cudaGetSymbolAddress((void**)&OFF, g_OFF);
    cudaGetSymbolAddress((void**)&LOG, g_LOG);
    cudaGetSymbolAddress((void**)&AOUT, g_AOUT);
    cudaGetSymbolAddress((void**)&X1, g_X1);
    cudaGetSymbolAddress((void**)&H, g_H);
    cudaGetSymbolAddress((void**)&Y, g_Y);

    const int M = TOK;
    const int MB = (M + 63) / 64;   // 416

    // 1. query = src + pos
    add_kernel<<<(TOK * D / 4 + 255) / 256, 256>>>(src, pos, Q, TOK * D / 4);
    // 2. value projection
    sgemm_bias<<<dim3(4, MB), 256>>>(src, Wv, bv, V, M, 256, 256, 0);
    // 3. offsets
    sgemm_bias<<<dim3(4, MB), 256>>>(Q, Woff, boff, OFF, M, 256, 256, 0);
    // 4. attention logits
    sgemm_bias<<<dim3(2, MB), 256>>>(Q, Wattn, battn, LOG, M, 128, 256, 0);
    // 5. deformable sampling
    sample_kernel<<<TOK, 256>>>(refp);
    // 6. output projection
    sgemm_bias<<<dim3(4, MB), 256>>>(AOUT, Wout, bout, Y, M, 256, 256, 0);
    // 7. first residual + LN
    resid_ln<<<(TOK + 7) / 8, 256>>>(src, Y, g1, be1, X1);
    // 8. FFN up + relu
    sgemm_bias<<<dim3(16, MB), 256>>>(X1, W1, b1, H, M, 1024, 256, 1);
    // 9. FFN down
    sgemm_bias<<<dim3(4, MB), 256>>>(H, W2, b2, Y, M, 256, 1024, 0);
    // 10. second residual + LN -> output
    resid_ln<<<(TOK + 7) / 8, 256>>>(X1, Y, g2, be2, out);
}

// round 3
// speedup vs baseline: 2.2217x; 2.2217x over previous
#include <cuda_runtime.h>
#include <math.h>
#include <stdint.h>

#define LEN 13294
#define TOK (2 * LEN)
#define D 256
#define NH 8
#define DH 32
#define DFF 1024
#define EPS 1e-5f

// ---------------- scratch (device globals; no allocation allowed) ----------------
__device__ float g_Q[TOK * D];      // src + pos
__device__ float g_V[TOK * D];      // value projection
__device__ float g_OFF[TOK * D];    // sampling offsets (NH*NL*NP*2 = 256)
__device__ float g_LOG[TOK * 128];  // attention logits (NH*NL*NP = 128)
__device__ float g_AOUT[TOK * D];   // deform-attn per-head output
__device__ float g_X1[TOK * D];     // after first residual+LN
__device__ float g_H[TOK * DFF];    // FFN hidden
__device__ float g_Y[TOK * D];      // generic 256-wide scratch

__constant__ int c_HW[4] = {100, 50, 25, 13};        // H==W per level
__constant__ int c_S[4]  = {0, 10000, 12500, 13125}; // level starts

// ---------------- elementwise add (float4) ----------------
__global__ __launch_bounds__(256) void add_kernel(const float* __restrict__ a,
                                                  const float* __restrict__ b,
                                                  float* __restrict__ o, int n4) {
    int i = blockIdx.x * blockDim.x + threadIdx.x;
    if (i >= n4) return;
    float4 va = ((const float4*)a)[i];
    float4 vb = ((const float4*)b)[i];
    va.x += vb.x; va.y += vb.y; va.z += vb.z; va.w += vb.w;
    ((float4*)o)[i] = va;
}

// ---------------- tf32 tensor-core GEMM ----------------
// C[M,N] = A[M,K] @ B[K,N] + bias, optional relu.
// 128x128x32 block tile, 256 threads (8 warps), warp tile 64x32 via
// mma.sync.m16n8k8.tf32. tf32 conversion happens at smem-store time.
// Conflict-free smem strides: As[m][36] (bank=4g+c), Bs[k][136] (bank=8c+g).

__device__ __forceinline__ uint32_t f2tf(float x) {
    uint32_t u;
    asm("cvt.rna.tf32.f32 %0, %1;" : "=r"(u) : "f"(x));
    return u;
}

__global__ __launch_bounds__(256, 2) void gemm_tf32(const float* __restrict__ A,
                                                    const float* __restrict__ Bw,
                                                    const float* __restrict__ bias,
                                                    float* __restrict__ C,
                                                    int M, int N, int K, int relu) {
    __shared__ uint32_t As[128][36];    // tf32 bits; stride 36: conflict-free frag loads
    __shared__ uint32_t Bs[32][136];    // tf32 bits; stride 136: conflict-free frag loads

    const int t = threadIdx.x;
    const int lane = t & 31;
    const int wid = t >> 5;
    const int warp_m = wid & 1;      // 0..1 -> 64-row slab
    const int warp_n = wid >> 1;     // 0..3 -> 32-col slab
    const int g = lane >> 2;         // 0..7
    const int c = lane & 3;          // 0..3

    const int row0 = blockIdx.y * 128;
    const int col0 = blockIdx.x * 128;

    // global staging indices
    const int a_row = t >> 3;        // 0..31 (+ i*32)
    const int a_kq  = (t & 7) * 4;
    const int b_kr  = t >> 5;        // 0..7 (+ i*8)
    const int b_nq  = (t & 31) * 4;

    float4 ra[4], rb[4];

    auto load_regs = [&](int k0) {
#pragma unroll
        for (int i = 0; i < 4; i++) {
            int r = a_row + i * 32;
            int gr = row0 + r;
            ra[i] = (gr < M) ? *(const float4*)&A[(size_t)gr * K + k0 + a_kq]
                             : make_float4(0.f, 0.f, 0.f, 0.f);
        }
#pragma unroll
        for (int i = 0; i < 4; i++) {
            int kr = b_kr + i * 8;
            rb[i] = *(const float4*)&Bw[(size_t)(k0 + kr) * N + col0 + b_nq];
        }
    };
    auto store_smem = [&]() {
#pragma unroll
        for (int i = 0; i < 4; i++) {
            uint32_t* p = &As[a_row + i * 32][a_kq];
            p[0] = f2tf(ra[i].x); p[1] = f2tf(ra[i].y);
            p[2] = f2tf(ra[i].z); p[3] = f2tf(ra[i].w);
        }
#pragma unroll
        for (int i = 0; i < 4; i++) {
            uint32_t* p = &Bs[b_kr + i * 8][b_nq];
            p[0] = f2tf(rb[i].x); p[1] = f2tf(rb[i].y);
            p[2] = f2tf(rb[i].z); p[3] = f2tf(rb[i].w);
        }
    };

    float acc[4][4][4];
#pragma unroll
    for (int mi = 0; mi < 4; mi++)
#pragma unroll
        for (int ni = 0; ni < 4; ni++)
#pragma unroll
            for (int r = 0; r < 4; r++) acc[mi][ni][r] = 0.f;

    load_regs(0);
    store_smem();
    __syncthreads();

    for (int k0 = 0; k0 < K; k0 += 32) {
        bool has_next = (k0 + 32) < K;
        if (has_next) load_regs(k0 + 32);

#pragma unroll
        for (int kk = 0; kk < 32; kk += 8) {
            uint32_t af[4][4], bf[4][2];
#pragma unroll
            for (int mi = 0; mi < 4; mi++) {
                int r0 = warp_m * 64 + mi * 16 + g;
                af[mi][0] = As[r0][kk + c];
                af[mi][1] = As[r0 + 8][kk + c];
                af[mi][2] = As[r0][kk + c + 4];
                af[mi][3] = As[r0 + 8][kk + c + 4];
            }
#pragma unroll
            for (int ni = 0; ni < 4; ni++) {
                int col = warp_n * 32 + ni * 8 + g;
                bf[ni][0] = Bs[kk + c][col];
                bf[ni][1] = Bs[kk + c + 4][col];
            }
#pragma unroll
            for (int mi = 0; mi < 4; mi++)
#pragma unroll
                for (int ni = 0; ni < 4; ni++) {
                    asm volatile(
                        "mma.sync.aligned.m16n8k8.row.col.f32.tf32.tf32.f32 "
                        "{%0,%1,%2,%3}, {%4,%5,%6,%7}, {%8,%9}, {%0,%1,%2,%3};"
                        : "+f"(acc[mi][ni][0]), "+f"(acc[mi][ni][1]),
                          "+f"(acc[mi][ni][2]), "+f"(acc[mi][ni][3])
                        : "r"(af[mi][0]), "r"(af[mi][1]), "r"(af[mi][2]), "r"(af[mi][3]),
                          "r"(bf[ni][0]), "r"(bf[ni][1]));
                }
        }

        if (has_next) {
            __syncthreads();
            store_smem();
            __syncthreads();
        }
    }

    // epilogue
#pragma unroll
    for (int mi = 0; mi < 4; mi++) {
#pragma unroll
        for (int ni = 0; ni < 4; ni++) {
            int gc = col0 + warp_n * 32 + ni * 8 + 2 * c;
            float b0 = bias[gc], b1 = bias[gc + 1];
            int gr0 = row0 + warp_m * 64 + mi * 16 + g;
            if (gr0 < M) {
                float2 v;
                v.x = acc[mi][ni][0] + b0;
                v.y = acc[mi][ni][1] + b1;
                if (relu) { v.x = fmaxf(v.x, 0.f); v.y = fmaxf(v.y, 0.f); }
                *(float2*)&C[(size_t)gr0 * N + gc] = v;
            }
            int gr1 = gr0 + 8;
            if (gr1 < M) {
                float2 v;
                v.x = acc[mi][ni][2] + b0;
                v.y = acc[mi][ni][3] + b1;
                if (relu) { v.x = fmaxf(v.x, 0.f); v.y = fmaxf(v.y, 0.f); }
                *(float2*)&C[(size_t)gr1 * N + gc] = v;
            }
        }
    }
}

// ---------------- deformable sampling: one warp per (token, head) ----------------
__global__ __launch_bounds__(256) void sample_kernel(const float* __restrict__ refpts) {
    int gidx = blockIdx.x * 8 + (threadIdx.x >> 5);
    int lane = threadIdx.x & 31;
    if (gidx >= TOK * NH) return;
    int t = gidx >> 3;       // token (b*LEN + q)
    int h = gidx & 7;
    int b = t / LEN;

    const float* lg = g_LOG + (size_t)t * 128 + h * 16;
    float m = -1e30f;
    float e[16];
#pragma unroll
    for (int i = 0; i < 16; i++) m = fmaxf(m, lg[i]);
    float s = 0.f;
#pragma unroll
    for (int i = 0; i < 16; i++) { e[i] = __expf(lg[i] - m); s += e[i]; }
    float inv = 1.f / s;

    const float* offp = g_OFF + (size_t)t * 256 + h * 32;
    float acc = 0.f;

#pragma unroll
    for (int l = 0; l < 4; l++) {
        int Wi = c_HW[l];
        int Hi = Wi;
        float Wf = (float)Wi, Hf = (float)Hi;
        float rx = refpts[(size_t)t * 8 + l * 2 + 0];
        float ry = refpts[(size_t)t * 8 + l * 2 + 1];
        const float* vbase = g_V + ((size_t)(b * LEN + c_S[l])) * 256 + h * 32;
#pragma unroll
        for (int p = 0; p < 4; p++) {
            float aw = e[l * 4 + p] * inv;
            float x = rx * Wf + offp[l * 8 + p * 2 + 0] - 0.5f;
            float y = ry * Hf + offp[l * 8 + p * 2 + 1] - 0.5f;
            float x0f = floorf(x), y0f = floorf(y);
            float dx = x - x0f, dy = y - y0f;
            int x0 = (int)x0f, y0 = (int)y0f;
            float w00 = (1.f - dx) * (1.f - dy) * aw;
            float w10 = dx * (1.f - dy) * aw;
            float w01 = (1.f - dx) * dy * aw;
            float w11 = dx * dy * aw;
            if (x0 >= 0 && x0 < Wi && y0 >= 0 && y0 < Hi)
                acc += w00 * vbase[(size_t)(y0 * Wi + x0) * 256 + lane];
            if (x0 + 1 >= 0 && x0 + 1 < Wi && y0 >= 0 && y0 < Hi)
                acc += w10 * vbase[(size_t)(y0 * Wi + x0 + 1) * 256 + lane];
            if (x0 >= 0 && x0 < Wi && y0 + 1 >= 0 && y0 + 1 < Hi)
                acc += w01 * vbase[(size_t)((y0 + 1) * Wi + x0) * 256 + lane];
            if (x0 + 1 >= 0 && x0 + 1 < Wi && y0 + 1 >= 0 && y0 + 1 < Hi)
                acc += w11 * vbase[(size_t)((y0 + 1) * Wi + x0 + 1) * 256 + lane];
        }
    }
    g_AOUT[(size_t)t * 256 + h * 32 + lane] = acc;
}

// ---------------- residual + layernorm: one warp per token, D=256 -----------------
__global__ __launch_bounds__(256) void resid_ln(const float* __restrict__ a,
                                                const float* __restrict__ r,
                                                const float* __restrict__ gam,
                                                const float* __restrict__ bet,
                                                float* __restrict__ out) {
    int t = blockIdx.x * 8 + (threadIdx.x >> 5);
    int lane = threadIdx.x & 31;
    if (t >= TOK) return;
    size_t base = (size_t)t * 256 + lane * 8;
    float v[8];
    float s = 0.f;
#pragma unroll
    for (int i = 0; i < 8; i++) {
        v[i] = a[base + i] + r[base + i];
        s += v[i];
    }
#pragma unroll
    for (int o = 16; o > 0; o >>= 1) s += __shfl_xor_sync(0xffffffffu, s, o);
    float mean = s * (1.f / 256.f);
    float s2 = 0.f;
#pragma unroll
    for (int i = 0; i < 8; i++) {
        float d = v[i] - mean;
        s2 += d * d;
    }
#pragma unroll
    for (int o = 16; o > 0; o >>= 1) s2 += __shfl_xor_sync(0xffffffffu, s2, o);
    float rstd = rsqrtf(s2 * (1.f / 256.f) + EPS);
#pragma unroll
    for (int i = 0; i < 8; i++) {
        int cidx = lane * 8 + i;
        out[base + i] = (v[i] - mean) * rstd * gam[cidx] + bet[cidx];
    }
}

// ---------------- launch ----------------
extern "C" void kernel_launch(void* const* d_in, const int* in_sizes, int n_in,
                              void* d_out, int out_size) {
    const float* src   = (const float*)d_in[0];
    const float* pos   = (const float*)d_in[1];
    const float* refp  = (const float*)d_in[2];
    const float* Wv    = (const float*)d_in[3];
    const float* bv    = (const float*)d_in[4];
    const float* Woff  = (const float*)d_in[5];
    const float* boff  = (const float*)d_in[6];
    const float* Wattn = (const float*)d_in[7];
    const float* battn = (const float*)d_in[8];
    const float* Wout  = (const float*)d_in[9];
    const float* bout  = (const float*)d_in[10];
    const float* W1    = (const float*)d_in[11];
    const float* b1    = (const float*)d_in[12];
    const float* W2    = (const float*)d_in[13];
    const float* b2    = (const float*)d_in[14];
    const float* g1    = (const float*)d_in[15];
    const float* be1   = (const float*)d_in[16];
    const float* g2    = (const float*)d_in[17];
    const float* be2   = (const float*)d_in[18];
    float* out = (float*)d_out;

    float *Q, *V, *OFF, *LOG, *AOUT, *X1, *H, *Y;
    cudaGetSymbolAddress((void**)&Q, g_Q);
    cudaGetSymbolAddress((void**)&V, g_V);
    cudaGetSymbolAddress((void**)&OFF, g_OFF);
    cudaGetSymbolAddress((void**)&LOG, g_LOG);
    cudaGetSymbolAddress((void**)&AOUT, g_AOUT);
    cudaGetSymbolAddress((void**)&X1, g_X1);
    cudaGetSymbolAddress((void**)&H, g_H);
    cudaGetSymbolAddress((void**)&Y, g_Y);

    const int M = TOK;
    const int MB = (M + 127) / 128;   // 208

    // 1. query = src + pos
    add_kernel<<<(TOK * D / 4 + 255) / 256, 256>>>(src, pos, Q, TOK * D / 4);
    // 2. value projection (src @ Wv)
    gemm_tf32<<<dim3(2, MB), 256>>>(src, Wv, bv, V, M, 256, 256, 0);
    // 3. offsets (Q @ Woff)
    gemm_tf32<<<dim3(2, MB), 256>>>(Q, Woff, boff, OFF, M, 256, 256, 0);
    // 4. attention logits (Q @ Wattn), N=128
    gemm_tf32<<<dim3(1, MB), 256>>>(Q, Wattn, battn, LOG, M, 128, 256, 0);
    // 5. deformable sampling
    sample_kernel<<<TOK, 256>>>(refp);
    // 6. output projection
    gemm_tf32<<<dim3(2, MB), 256>>>(AOUT, Wout, bout, Y, M, 256, 256, 0);
    // 7. first residual + LN
    resid_ln<<<(TOK + 7) / 8, 256>>>(src, Y, g1, be1, X1);
    // 8. FFN up + relu
    gemm_tf32<<<dim3(8, MB), 256>>>(X1, W1, b1, H, M, 1024, 256, 1);
    // 9. FFN down
    gemm_tf32<<<dim3(2, MB), 256>>>(H, W2, b2, Y, M, 256, 1024, 0);
    // 10. second residual + LN -> output
    resid_ln<<<(TOK + 7) / 8, 256>>>(X1, Y, g2, be2, out);
}